// round 1
// baseline (speedup 1.0000x reference)
#include <cuda_runtime.h>
#include <math.h>

#define B_  8192
#define DE_ 256
#define DA_ 32
#define F_  2048
#define H_  2048

// Scratch (device globals: allocation-free rule)
__device__ float g_x[(size_t)B_ * 4096];     // [feat_o | feat_a]
__device__ float g_gi[(size_t)B_ * 6144];
__device__ float g_gh[(size_t)B_ * 6144];
__device__ float g_last[(size_t)B_ * 4096];  // [feat_post | h1]

__device__ __forceinline__ unsigned f2tf(float x) {
    unsigned r;
    asm("cvt.rna.tf32.f32 %0, %1;" : "=r"(r) : "f"(x));
    return r;
}

__device__ __forceinline__ void mma_tf32(float* c, const unsigned* a, const unsigned* b) {
    asm volatile(
        "mma.sync.aligned.m16n8k8.row.col.f32.tf32.tf32.f32 "
        "{%0,%1,%2,%3}, {%4,%5,%6,%7}, {%8,%9}, {%0,%1,%2,%3};"
        : "+f"(c[0]), "+f"(c[1]), "+f"(c[2]), "+f"(c[3])
        : "r"(a[0]), "r"(a[1]), "r"(a[2]), "r"(a[3]), "r"(b[0]), "r"(b[1]));
}

// C[m, coff+n] = act( A[m,:K] . W[n,:K] + bias[n] )
// A: row-major, leading dim lda.  W: [N][K] row-major, leading dim ldw.
// ACT: 0=none, 1=relu, 2=tanh
// BN: 128 (main) or 32 (action head). BM=128, BK=32 fixed.
template<int ACT, int BN>
__global__ __launch_bounds__(256)
void gemm_tf32_kernel(const float* __restrict__ A, int lda,
                      const float* __restrict__ W, int ldw,
                      const float* __restrict__ bias,
                      float* __restrict__ C, int ldc, int coff,
                      int K)
{
    constexpr int BM = 128, BK = 32, PAD = 4, LD = BK + PAD;
    __shared__ float As[BM][LD];
    __shared__ float Bs[BN][LD];

    const int m0 = blockIdx.y * BM;
    const int n0 = blockIdx.x * BN;
    const int tid  = threadIdx.x;
    const int warp = tid >> 5;
    const int lane = tid & 31;
    const int gid  = lane >> 2;   // 0..7
    const int tig  = lane & 3;    // 0..3

    constexpr int MI = (BN == 128) ? 4 : 1;   // 16-row mma tiles per warp
    constexpr int NI = 4;                      // 8-col mma tiles per warp
    const int wm = (BN == 128) ? (warp & 1) * 64 : warp * 16;
    const int wn = (BN == 128) ? (warp >> 1) * 32 : 0;

    float acc[MI][NI][4];
#pragma unroll
    for (int i = 0; i < MI; i++)
#pragma unroll
        for (int j = 0; j < NI; j++)
#pragma unroll
            for (int v = 0; v < 4; v++) acc[i][j][v] = 0.0f;

    const int lrow = tid >> 3;         // 0..31
    const int lk4  = (tid & 7) * 4;    // 0,4,...,28

    for (int k0 = 0; k0 < K; k0 += BK) {
        // Stage A (128 x 32) as tf32 bits
#pragma unroll
        for (int i = 0; i < 4; i++) {
            const int r = lrow + i * 32;
            const float4 v = *reinterpret_cast<const float4*>(
                &A[(long)(m0 + r) * lda + k0 + lk4]);
            As[r][lk4 + 0] = __uint_as_float(f2tf(v.x));
            As[r][lk4 + 1] = __uint_as_float(f2tf(v.y));
            As[r][lk4 + 2] = __uint_as_float(f2tf(v.z));
            As[r][lk4 + 3] = __uint_as_float(f2tf(v.w));
        }
        // Stage B = W tile (BN x 32)
#pragma unroll
        for (int i = 0; i < BN / 32; i++) {
            const int r = lrow + i * 32;
            const float4 v = *reinterpret_cast<const float4*>(
                &W[(long)(n0 + r) * ldw + k0 + lk4]);
            Bs[r][lk4 + 0] = __uint_as_float(f2tf(v.x));
            Bs[r][lk4 + 1] = __uint_as_float(f2tf(v.y));
            Bs[r][lk4 + 2] = __uint_as_float(f2tf(v.z));
            Bs[r][lk4 + 3] = __uint_as_float(f2tf(v.w));
        }
        __syncthreads();

#pragma unroll
        for (int kk = 0; kk < BK; kk += 8) {
            unsigned a[MI][4];
            unsigned b[NI][2];
#pragma unroll
            for (int mi = 0; mi < MI; mi++) {
                const int mr = wm + mi * 16;
                a[mi][0] = __float_as_uint(As[mr + gid    ][kk + tig    ]);
                a[mi][1] = __float_as_uint(As[mr + 8 + gid][kk + tig    ]);
                a[mi][2] = __float_as_uint(As[mr + gid    ][kk + 4 + tig]);
                a[mi][3] = __float_as_uint(As[mr + 8 + gid][kk + 4 + tig]);
            }
#pragma unroll
            for (int ni = 0; ni < NI; ni++) {
                const int nr = wn + ni * 8;
                b[ni][0] = __float_as_uint(Bs[nr + gid][kk + tig    ]);
                b[ni][1] = __float_as_uint(Bs[nr + gid][kk + 4 + tig]);
            }
#pragma unroll
            for (int mi = 0; mi < MI; mi++)
#pragma unroll
                for (int ni = 0; ni < NI; ni++)
                    mma_tf32(acc[mi][ni], a[mi], b[ni]);
        }
        __syncthreads();
    }

    // Epilogue: bias + activation, float2 stores
#pragma unroll
    for (int mi = 0; mi < MI; mi++) {
#pragma unroll
        for (int ni = 0; ni < NI; ni++) {
            const int col = n0 + wn + ni * 8 + tig * 2;
            const float b0 = bias[col];
            const float b1 = bias[col + 1];
            const int r0 = m0 + wm + mi * 16 + gid;
            const int r1 = r0 + 8;
            float v00 = acc[mi][ni][0] + b0;
            float v01 = acc[mi][ni][1] + b1;
            float v10 = acc[mi][ni][2] + b0;
            float v11 = acc[mi][ni][3] + b1;
            if (ACT == 1) {
                v00 = fmaxf(v00, 0.f); v01 = fmaxf(v01, 0.f);
                v10 = fmaxf(v10, 0.f); v11 = fmaxf(v11, 0.f);
            } else if (ACT == 2) {
                v00 = tanhf(v00); v01 = tanhf(v01);
                v10 = tanhf(v10); v11 = tanhf(v11);
            }
            *reinterpret_cast<float2*>(&C[(long)r0 * ldc + coff + col]) =
                make_float2(v00, v01);
            *reinterpret_cast<float2*>(&C[(long)r1 * ldc + coff + col]) =
                make_float2(v10, v11);
        }
    }
}

// Elementwise GRU gates -> next_hidden into d_out, h1 into g_last[:, 2048:]
__global__ __launch_bounds__(256)
void gru_kernel(const float* __restrict__ state, float* __restrict__ out)
{
    const int idx = blockIdx.x * blockDim.x + threadIdx.x;  // over B*H
    const int m = idx >> 11;        // /2048
    const int n = idx & 2047;
    const float* gi = g_gi + (long)m * 6144;
    const float* gh = g_gh + (long)m * 6144;
    const float h0 = state[(long)m * (DE_ + H_) + DE_ + n];

    const float r = 1.0f / (1.0f + expf(-(gi[n] + gh[n])));
    const float z = 1.0f / (1.0f + expf(-(gi[2048 + n] + gh[2048 + n])));
    const float nn = tanhf(gi[4096 + n] + r * gh[4096 + n]);
    const float h1 = (1.0f - z) * nn + z * h0;

    out[(long)B_ * DA_ + (long)m * H_ + n] = 0.5f * h0 + 0.5f * h1;
    g_last[(long)m * 4096 + 2048 + n] = h1;
}

extern "C" void kernel_launch(void* const* d_in, const int* in_sizes, int n_in,
                              void* d_out, int out_size)
{
    const float* state  = (const float*)d_in[0];
    const float* pa     = (const float*)d_in[1];
    const float* W_o    = (const float*)d_in[2];
    const float* b_o    = (const float*)d_in[3];
    const float* W_a    = (const float*)d_in[4];
    const float* b_a    = (const float*)d_in[5];
    const float* W_post = (const float*)d_in[6];
    const float* b_post = (const float*)d_in[7];
    const float* W_ih   = (const float*)d_in[8];
    const float* W_hh   = (const float*)d_in[9];
    const float* b_ih   = (const float*)d_in[10];
    const float* b_hh   = (const float*)d_in[11];
    const float* W3     = (const float*)d_in[12];
    const float* b3     = (const float*)d_in[13];
    float* out = (float*)d_out;

    float *x, *gi, *gh, *last;
    cudaGetSymbolAddress((void**)&x,    g_x);
    cudaGetSymbolAddress((void**)&gi,   g_gi);
    cudaGetSymbolAddress((void**)&gh,   g_gh);
    cudaGetSymbolAddress((void**)&last, g_last);

    const dim3 blk(256);

    // feat_o = relu(env @ W_o^T + b_o) -> x[:, 0:2048]
    gemm_tf32_kernel<1, 128><<<dim3(F_ / 128, B_ / 128), blk>>>(
        state, DE_ + H_, W_o, DE_, b_o, x, 4096, 0, DE_);
    // feat_a = relu(pa @ W_a^T + b_a) -> x[:, 2048:4096]
    gemm_tf32_kernel<1, 128><<<dim3(F_ / 128, B_ / 128), blk>>>(
        pa, DA_, W_a, DA_, b_a, x, 4096, 2048, DA_);
    // feat_post = relu(env @ W_post^T + b_post) -> last[:, 0:2048]
    gemm_tf32_kernel<1, 128><<<dim3(F_ / 128, B_ / 128), blk>>>(
        state, DE_ + H_, W_post, DE_, b_post, last, 4096, 0, DE_);

    // gi = x @ W_ih^T + b_ih   (8192 x 6144, K=4096)
    gemm_tf32_kernel<0, 128><<<dim3(6144 / 128, B_ / 128), blk>>>(
        x, 4096, W_ih, 4096, b_ih, gi, 6144, 0, 4096);
    // gh = h0 @ W_hh^T + b_hh  (8192 x 6144, K=2048)
    gemm_tf32_kernel<0, 128><<<dim3(6144 / 128, B_ / 128), blk>>>(
        state + DE_, DE_ + H_, W_hh, H_, b_hh, gh, 6144, 0, H_);

    // GRU gates: next_hidden -> out[B*DA:], h1 -> last[:, 2048:]
    gru_kernel<<<(B_ * H_) / 256, blk>>>(state, out);

    // action = tanh(last @ W3^T + b3) -> out[0 : B*DA]
    gemm_tf32_kernel<2, 32><<<dim3(1, B_ / 128), blk>>>(
        last, 4096, W3, 4096, b3, out, DA_, 0, 4096);
}

// round 2
// speedup vs baseline: 1.3681x; 1.3681x over previous
#include <cuda_runtime.h>
#include <math.h>

#define B_  8192
#define DE_ 256
#define DA_ 32
#define F_  2048
#define H_  2048

// ---------------- scratch (device globals: allocation-free rule) ----------------
__device__ float g_x[(size_t)B_ * 4096];     // [feat_o | feat_a]   (tf32-rounded)
__device__ float g_gi[(size_t)B_ * 6144];
__device__ float g_gh[(size_t)B_ * 6144];
__device__ float g_last[(size_t)B_ * 4096];  // [feat_post | h1]    (tf32-rounded)
// tf32-rounded operand copies
__device__ float g_Wih_r[(size_t)6144 * 4096];
__device__ float g_Whh_r[(size_t)6144 * 2048];
__device__ float g_h0r[(size_t)B_ * 2048];
__device__ float g_envr[(size_t)B_ * 256];
__device__ float g_par[(size_t)B_ * 32];
__device__ float g_Wo_r[(size_t)2048 * 256];
__device__ float g_Wa_r[(size_t)2048 * 32];
__device__ float g_Wpost_r[(size_t)2048 * 256];

__device__ __forceinline__ unsigned f2tf(float x) {
    unsigned r;
    asm("cvt.rna.tf32.f32 %0, %1;" : "=r"(r) : "f"(x));
    return r;
}

__device__ __forceinline__ void mma_tf32(float* c, const unsigned* a, const unsigned* b) {
    asm volatile(
        "mma.sync.aligned.m16n8k8.row.col.f32.tf32.tf32.f32 "
        "{%0,%1,%2,%3}, {%4,%5,%6,%7}, {%8,%9}, {%0,%1,%2,%3};"
        : "+f"(c[0]), "+f"(c[1]), "+f"(c[2]), "+f"(c[3])
        : "r"(a[0]), "r"(a[1]), "r"(a[2]), "r"(a[3]), "r"(b[0]), "r"(b[1]));
}

// ================= pipelined TF32 GEMM =================
// C[m, coff+n] = act( A[m,:K] . W[n,:K] + bias[n] )
// Inputs A, W MUST already be tf32-rounded (low 13 mantissa bits zero).
// ACT: 0=none 1=relu.  ROUND: round outputs to tf32 (for GEMM-operand outputs).
template<int ACT, int ROUND>
__global__ __launch_bounds__(256, 2)
void gemm_pipe(const float* __restrict__ A, int lda,
               const float* __restrict__ W, int ldw,
               const float* __restrict__ bias,
               float* __restrict__ C, int ldc, int coff, int K)
{
    constexpr int BM = 128, BN = 128, BK = 32, LD = 36, STAGES = 3;
    extern __shared__ float smem[];
    float* As = smem;                         // [STAGES][BM][LD]
    float* Bs = smem + STAGES * BM * LD;      // [STAGES][BN][LD]
    const unsigned sA = (unsigned)__cvta_generic_to_shared(As);
    const unsigned sB = (unsigned)__cvta_generic_to_shared(Bs);

    const int m0 = blockIdx.y * BM;
    const int n0 = blockIdx.x * BN;
    const int tid = threadIdx.x;
    const int warp = tid >> 5;
    const int lane = tid & 31;
    const int wm = (warp & 1) * 64;
    const int wn = (warp >> 1) * 32;

    const int kIters = K / BK;

    // ldmatrix per-lane address components
    const int lrow8 = lane & 7;
    const int q = lane >> 3;
    const int aRow = (q & 1) * 8 + lrow8;   // A: reg order a0,a1,a2,a3
    const int aCol = (q >> 1) * 4;
    const int bRow = (q >> 1) * 8 + lrow8;  // B: two n-tiles per x4
    const int bCol = (q & 1) * 4;

    float acc[4][4][4];
#pragma unroll
    for (int i = 0; i < 4; i++)
#pragma unroll
        for (int j = 0; j < 4; j++)
#pragma unroll
            for (int v = 0; v < 4; v++) acc[i][j][v] = 0.0f;

    auto issueStage = [&](int it, int stage) {
        if (it < kIters) {
            const long k0 = (long)it * BK;
            const unsigned dstA = sA + stage * (BM * LD * 4);
            const unsigned dstB = sB + stage * (BN * LD * 4);
#pragma unroll
            for (int i = 0; i < 4; i++) {
                const int chunk = tid + i * 256;
                const int r = chunk >> 3, cc = chunk & 7;
                const float* src = A + (long)(m0 + r) * lda + k0 + cc * 4;
                const unsigned dst = dstA + (unsigned)(r * LD + cc * 4) * 4u;
                asm volatile("cp.async.cg.shared.global [%0], [%1], 16;\n"
                             :: "r"(dst), "l"(src));
            }
#pragma unroll
            for (int i = 0; i < 4; i++) {
                const int chunk = tid + i * 256;
                const int r = chunk >> 3, cc = chunk & 7;
                const float* src = W + (long)(n0 + r) * ldw + k0 + cc * 4;
                const unsigned dst = dstB + (unsigned)(r * LD + cc * 4) * 4u;
                asm volatile("cp.async.cg.shared.global [%0], [%1], 16;\n"
                             :: "r"(dst), "l"(src));
            }
        }
        asm volatile("cp.async.commit_group;\n");
    };

    issueStage(0, 0);
    issueStage(1, 1);

    for (int it = 0; it < kIters; it++) {
        asm volatile("cp.async.wait_group 1;\n");
        __syncthreads();
        const int stage = it % STAGES;
        issueStage(it + 2, (it + 2) % STAGES);

        const unsigned baseA = sA + stage * (BM * LD * 4);
        const unsigned baseB = sB + stage * (BN * LD * 4);

#pragma unroll
        for (int kk = 0; kk < BK; kk += 8) {
            unsigned a[4][4], b[4][2];
#pragma unroll
            for (int mi = 0; mi < 4; mi++) {
                const unsigned addr =
                    baseA + (unsigned)(((wm + mi * 16 + aRow) * LD + kk + aCol) << 2);
                asm volatile(
                    "ldmatrix.sync.aligned.m8n8.x4.shared.b16 {%0,%1,%2,%3}, [%4];"
                    : "=r"(a[mi][0]), "=r"(a[mi][1]), "=r"(a[mi][2]), "=r"(a[mi][3])
                    : "r"(addr));
            }
#pragma unroll
            for (int np = 0; np < 2; np++) {
                const unsigned addr =
                    baseB + (unsigned)(((wn + np * 16 + bRow) * LD + kk + bCol) << 2);
                asm volatile(
                    "ldmatrix.sync.aligned.m8n8.x4.shared.b16 {%0,%1,%2,%3}, [%4];"
                    : "=r"(b[2 * np][0]), "=r"(b[2 * np][1]),
                      "=r"(b[2 * np + 1][0]), "=r"(b[2 * np + 1][1])
                    : "r"(addr));
            }
#pragma unroll
            for (int mi = 0; mi < 4; mi++)
#pragma unroll
                for (int ni = 0; ni < 4; ni++)
                    mma_tf32(acc[mi][ni], a[mi], b[ni]);
        }
    }

    // epilogue
    const int gid = lane >> 2;
    const int tig = lane & 3;
#pragma unroll
    for (int mi = 0; mi < 4; mi++) {
#pragma unroll
        for (int ni = 0; ni < 4; ni++) {
            const int col = n0 + wn + ni * 8 + tig * 2;
            const float b0 = bias[col];
            const float b1 = bias[col + 1];
            const int r0 = m0 + wm + mi * 16 + gid;
            const int r1 = r0 + 8;
            float v00 = acc[mi][ni][0] + b0;
            float v01 = acc[mi][ni][1] + b1;
            float v10 = acc[mi][ni][2] + b0;
            float v11 = acc[mi][ni][3] + b1;
            if (ACT == 1) {
                v00 = fmaxf(v00, 0.f); v01 = fmaxf(v01, 0.f);
                v10 = fmaxf(v10, 0.f); v11 = fmaxf(v11, 0.f);
            }
            if (ROUND) {
                v00 = __uint_as_float(f2tf(v00)); v01 = __uint_as_float(f2tf(v01));
                v10 = __uint_as_float(f2tf(v10)); v11 = __uint_as_float(f2tf(v11));
            }
            *reinterpret_cast<float2*>(&C[(long)r0 * ldc + coff + col]) =
                make_float2(v00, v01);
            *reinterpret_cast<float2*>(&C[(long)r1 * ldc + coff + col]) =
                make_float2(v10, v11);
        }
    }
}

// ================= small action-head GEMM (N=32, tanh) — round-1 style =================
__global__ __launch_bounds__(256)
void gemm_head(const float* __restrict__ A, int lda,
               const float* __restrict__ W, int ldw,
               const float* __restrict__ bias,
               float* __restrict__ C, int ldc, int K)
{
    constexpr int BM = 128, BN = 32, BK = 32, LD = 36;
    __shared__ float As[BM][LD];
    __shared__ float Bs[BN][LD];

    const int m0 = blockIdx.y * BM;
    const int tid = threadIdx.x;
    const int warp = tid >> 5;
    const int lane = tid & 31;
    const int gid = lane >> 2;
    const int tig = lane & 3;
    const int wm = warp * 16;

    float acc[4][4];
#pragma unroll
    for (int j = 0; j < 4; j++)
#pragma unroll
        for (int v = 0; v < 4; v++) acc[j][v] = 0.0f;

    const int lrow = tid >> 3;
    const int lk4 = (tid & 7) * 4;

    for (int k0 = 0; k0 < K; k0 += BK) {
#pragma unroll
        for (int i = 0; i < 4; i++) {
            const int r = lrow + i * 32;
            const float4 v = *reinterpret_cast<const float4*>(
                &A[(long)(m0 + r) * lda + k0 + lk4]);
            As[r][lk4 + 0] = __uint_as_float(f2tf(v.x));
            As[r][lk4 + 1] = __uint_as_float(f2tf(v.y));
            As[r][lk4 + 2] = __uint_as_float(f2tf(v.z));
            As[r][lk4 + 3] = __uint_as_float(f2tf(v.w));
        }
        {
            const int r = lrow;
            if (r < BN) {
                const float4 v = *reinterpret_cast<const float4*>(
                    &W[(long)r * ldw + k0 + lk4]);
                Bs[r][lk4 + 0] = __uint_as_float(f2tf(v.x));
                Bs[r][lk4 + 1] = __uint_as_float(f2tf(v.y));
                Bs[r][lk4 + 2] = __uint_as_float(f2tf(v.z));
                Bs[r][lk4 + 3] = __uint_as_float(f2tf(v.w));
            }
        }
        __syncthreads();

#pragma unroll
        for (int kk = 0; kk < BK; kk += 8) {
            unsigned a[4];
            a[0] = __float_as_uint(As[wm + gid    ][kk + tig    ]);
            a[1] = __float_as_uint(As[wm + 8 + gid][kk + tig    ]);
            a[2] = __float_as_uint(As[wm + gid    ][kk + 4 + tig]);
            a[3] = __float_as_uint(As[wm + 8 + gid][kk + 4 + tig]);
#pragma unroll
            for (int ni = 0; ni < 4; ni++) {
                unsigned b[2];
                b[0] = __float_as_uint(Bs[ni * 8 + gid][kk + tig    ]);
                b[1] = __float_as_uint(Bs[ni * 8 + gid][kk + 4 + tig]);
                mma_tf32(acc[ni], a, b);
            }
        }
        __syncthreads();
    }

#pragma unroll
    for (int ni = 0; ni < 4; ni++) {
        const int col = ni * 8 + tig * 2;
        const float b0 = bias[col];
        const float b1 = bias[col + 1];
        const int r0 = m0 + wm + gid;
        const int r1 = r0 + 8;
        C[(long)r0 * ldc + col]     = tanhf(acc[ni][0] + b0);
        C[(long)r0 * ldc + col + 1] = tanhf(acc[ni][1] + b1);
        C[(long)r1 * ldc + col]     = tanhf(acc[ni][2] + b0);
        C[(long)r1 * ldc + col + 1] = tanhf(acc[ni][3] + b1);
    }
}

// ================= GRU elementwise =================
__global__ __launch_bounds__(256)
void gru_kernel(const float* __restrict__ state, float* __restrict__ out)
{
    const int idx = blockIdx.x * blockDim.x + threadIdx.x;  // over B*H
    const int m = idx >> 11;
    const int n = idx & 2047;
    const float* gi = g_gi + (long)m * 6144;
    const float* gh = g_gh + (long)m * 6144;
    const float h0 = state[(long)m * (DE_ + H_) + DE_ + n];

    const float r = 1.0f / (1.0f + expf(-(gi[n] + gh[n])));
    const float z = 1.0f / (1.0f + expf(-(gi[2048 + n] + gh[2048 + n])));
    const float nn = tanhf(gi[4096 + n] + r * gh[4096 + n]);
    const float h1 = (1.0f - z) * nn + z * h0;

    out[(long)B_ * DA_ + (long)m * H_ + n] = 0.5f * h0 + 0.5f * h1;
    g_last[(long)m * 4096 + 2048 + n] = __uint_as_float(f2tf(h1));
}

// ================= tf32-rounding passes =================
__global__ __launch_bounds__(256)
void cvt_kernel(const float* __restrict__ in, float* __restrict__ out, int n4)
{
    const int i = blockIdx.x * blockDim.x + threadIdx.x;
    if (i < n4) {
        const float4 v = reinterpret_cast<const float4*>(in)[i];
        float4 o;
        o.x = __uint_as_float(f2tf(v.x));
        o.y = __uint_as_float(f2tf(v.y));
        o.z = __uint_as_float(f2tf(v.z));
        o.w = __uint_as_float(f2tf(v.w));
        reinterpret_cast<float4*>(out)[i] = o;
    }
}

// split state -> rounded env [B,256] and rounded h0 [B,2048]
__global__ __launch_bounds__(256)
void split_state_kernel(const float* __restrict__ state,
                        float* __restrict__ envr, float* __restrict__ h0r)
{
    const int i = blockIdx.x * blockDim.x + threadIdx.x;  // over B * 576 float4
    if (i >= B_ * 576) return;
    const int row = i / 576;
    const int c4 = (i % 576) * 4;
    const float4 v = *reinterpret_cast<const float4*>(state + (long)row * 2304 + c4);
    float4 o;
    o.x = __uint_as_float(f2tf(v.x));
    o.y = __uint_as_float(f2tf(v.y));
    o.z = __uint_as_float(f2tf(v.z));
    o.w = __uint_as_float(f2tf(v.w));
    if (c4 < 256)
        *reinterpret_cast<float4*>(envr + (long)row * 256 + c4) = o;
    else
        *reinterpret_cast<float4*>(h0r + (long)row * 2048 + (c4 - 256)) = o;
}

extern "C" void kernel_launch(void* const* d_in, const int* in_sizes, int n_in,
                              void* d_out, int out_size)
{
    const float* state  = (const float*)d_in[0];
    const float* pa     = (const float*)d_in[1];
    const float* W_o    = (const float*)d_in[2];
    const float* b_o    = (const float*)d_in[3];
    const float* W_a    = (const float*)d_in[4];
    const float* b_a    = (const float*)d_in[5];
    const float* W_post = (const float*)d_in[6];
    const float* b_post = (const float*)d_in[7];
    const float* W_ih   = (const float*)d_in[8];
    const float* W_hh   = (const float*)d_in[9];
    const float* b_ih   = (const float*)d_in[10];
    const float* b_hh   = (const float*)d_in[11];
    const float* W3     = (const float*)d_in[12];
    const float* b3     = (const float*)d_in[13];
    float* out = (float*)d_out;

    float *x, *gi, *gh, *last, *Wih_r, *Whh_r, *h0r, *envr, *par, *Wo_r, *Wa_r, *Wpost_r;
    cudaGetSymbolAddress((void**)&x,      g_x);
    cudaGetSymbolAddress((void**)&gi,     g_gi);
    cudaGetSymbolAddress((void**)&gh,     g_gh);
    cudaGetSymbolAddress((void**)&last,   g_last);
    cudaGetSymbolAddress((void**)&Wih_r,  g_Wih_r);
    cudaGetSymbolAddress((void**)&Whh_r,  g_Whh_r);
    cudaGetSymbolAddress((void**)&h0r,    g_h0r);
    cudaGetSymbolAddress((void**)&envr,   g_envr);
    cudaGetSymbolAddress((void**)&par,    g_par);
    cudaGetSymbolAddress((void**)&Wo_r,   g_Wo_r);
    cudaGetSymbolAddress((void**)&Wa_r,   g_Wa_r);
    cudaGetSymbolAddress((void**)&Wpost_r,g_Wpost_r);

    const int SMEM = 3 * (128 + 128) * 36 * 4;  // 110592 B
    cudaFuncSetAttribute(gemm_pipe<1, 1>, cudaFuncAttributeMaxDynamicSharedMemorySize, SMEM);
    cudaFuncSetAttribute(gemm_pipe<0, 0>, cudaFuncAttributeMaxDynamicSharedMemorySize, SMEM);

    const dim3 blk(256);

    // ---- tf32 rounding passes ----
    split_state_kernel<<<(B_ * 576 + 255) / 256, blk>>>(state, envr, h0r);
    cvt_kernel<<<(B_ * 32 / 4 + 255) / 256, blk>>>(pa, par, B_ * 32 / 4);
    cvt_kernel<<<(2048 * 256 / 4 + 255) / 256, blk>>>(W_o, Wo_r, 2048 * 256 / 4);
    cvt_kernel<<<(2048 * 32 / 4 + 255) / 256, blk>>>(W_a, Wa_r, 2048 * 32 / 4);
    cvt_kernel<<<(2048 * 256 / 4 + 255) / 256, blk>>>(W_post, Wpost_r, 2048 * 256 / 4);
    cvt_kernel<<<(6144 * 4096 / 4 + 255) / 256, blk>>>(W_ih, Wih_r, 6144 * 4096 / 4);
    cvt_kernel<<<(6144 * 2048 / 4 + 255) / 256, blk>>>(W_hh, Whh_r, 6144 * 2048 / 4);

    // ---- feature GEMMs (relu, round outputs) ----
    gemm_pipe<1, 1><<<dim3(16, 64), blk, SMEM>>>(envr, 256, Wo_r, 256, b_o, x, 4096, 0, 256);
    gemm_pipe<1, 1><<<dim3(16, 64), blk, SMEM>>>(par, 32, Wa_r, 32, b_a, x, 4096, 2048, 32);
    gemm_pipe<1, 1><<<dim3(16, 64), blk, SMEM>>>(envr, 256, Wpost_r, 256, b_post, last, 4096, 0, 256);

    // ---- big gate GEMMs ----
    gemm_pipe<0, 0><<<dim3(48, 64), blk, SMEM>>>(x, 4096, Wih_r, 4096, b_ih, gi, 6144, 0, 4096);
    gemm_pipe<0, 0><<<dim3(48, 64), blk, SMEM>>>(h0r, 2048, Whh_r, 2048, b_hh, gh, 6144, 0, 2048);

    // ---- GRU elementwise ----
    gru_kernel<<<(B_ * H_) / 256, blk>>>(state, out);

    // ---- action head ----
    gemm_head<<<dim3(1, 64), blk>>>(last, 4096, W3, 4096, b3, out, DA_, 4096);
}

// round 5
// speedup vs baseline: 2.6095x; 1.9074x over previous
#include <cuda_runtime.h>
#include <cuda_fp16.h>
#include <math.h>
#include <stdint.h>

#define B_  8192
#define DE_ 256
#define DA_ 32
#define F_  2048
#define H_  2048

// ---------------- scratch (device globals: allocation-free rule) ----------------
__device__ float  g_gi[(size_t)B_ * 6144];
__device__ float  g_gh[(size_t)B_ * 6144];
__device__ __half g_xh[(size_t)B_ * 4096];      // [feat_o | feat_a]
__device__ __half g_lasth[(size_t)B_ * 4096];   // [feat_post | h1]
__device__ __half g_Wih_h[(size_t)6144 * 4096];
__device__ __half g_Whh_h[(size_t)6144 * 2048];
__device__ __half g_h0h[(size_t)B_ * 2048];
__device__ __half g_envh[(size_t)B_ * 256];
__device__ __half g_pah[(size_t)B_ * 64];       // K padded 32 -> 64
__device__ __half g_Woh[(size_t)2048 * 256];
__device__ __half g_Wah[(size_t)2048 * 64];     // K padded 32 -> 64
__device__ __half g_Wposth[(size_t)2048 * 256];
__device__ __half g_W3h[(size_t)32 * 4096];

__device__ __forceinline__ uint32_t smem_u32(const void* p) {
    uint32_t a;
    asm("{ .reg .u64 t; cvta.to.shared.u64 t, %1; cvt.u32.u64 %0, t; }"
        : "=r"(a) : "l"(p));
    return a;
}

__device__ __forceinline__ void mma_fp16(float* c, const unsigned* a, const unsigned* b) {
    asm volatile(
        "mma.sync.aligned.m16n8k16.row.col.f32.f16.f16.f32 "
        "{%0,%1,%2,%3}, {%4,%5,%6,%7}, {%8,%9}, {%0,%1,%2,%3};"
        : "+f"(c[0]), "+f"(c[1]), "+f"(c[2]), "+f"(c[3])
        : "r"(a[0]), "r"(a[1]), "r"(a[2]), "r"(a[3]), "r"(b[0]), "r"(b[1]));
}

// ================= pipelined FP16 GEMM =================
// C[m, coff+n] = act( A[m,:K] . W[n,:K] + bias[n] )
// BM=128, BN=128, BK=64 halves. 3-stage cp.async. 256 threads, 8 warps (64x32 warp tile).
// ACT: 0=none 1=relu.  OUTH: 1 -> store __half, 0 -> store float.
template<int ACT, int OUTH>
__global__ __launch_bounds__(256, 2)
void gemm_h(const __half* __restrict__ A, int lda,
            const __half* __restrict__ W, int ldw,
            const float* __restrict__ bias,
            void* __restrict__ Cv, int ldc, int coff, int kIters)
{
    constexpr int BM = 128, BN = 128, BK = 64, LDH = 72, STAGES = 3;
    constexpr int OPB = BM * LDH * 2;          // bytes per operand per stage (18432)
    extern __shared__ __half smh[];
    const unsigned sA = smem_u32(smh);
    const unsigned sB = sA + STAGES * OPB;

    const int m0 = blockIdx.y * BM;
    const int n0 = blockIdx.x * BN;
    const int tid = threadIdx.x;
    const int warp = tid >> 5;
    const int lane = tid & 31;
    const int wm = (warp & 1) * 64;
    const int wn = (warp >> 1) * 32;

    // ldmatrix lane addressing
    const int g = lane >> 3;
    const int r8 = lane & 7;
    const int aRow = (g & 1) * 8 + r8;    // A regs: (gid,k0),(gid+8,k0),(gid,k8),(gid+8,k8)
    const int aColH = (g >> 1) * 8;
    const int bRow = (g >> 1) * 8 + r8;   // B regs: (n0,k0),(n0,k8),(n8,k0),(n8,k8)
    const int bColH = (g & 1) * 8;

    float acc[4][4][4];
#pragma unroll
    for (int i = 0; i < 4; i++)
#pragma unroll
        for (int j = 0; j < 4; j++)
#pragma unroll
            for (int v = 0; v < 4; v++) acc[i][j][v] = 0.0f;

    auto issueStage = [&](int it, int stage) {
        if (it < kIters) {
            const long k0 = (long)it * BK;
            const unsigned dA = sA + stage * OPB;
            const unsigned dB = sB + stage * OPB;
#pragma unroll
            for (int i = 0; i < 4; i++) {
                const int ch = tid + i * 256;       // 1024 chunks of 16B
                const int r = ch >> 3, c = ch & 7;
                const __half* src = A + (long)(m0 + r) * lda + k0 + c * 8;
                const unsigned dst = dA + (unsigned)(r * LDH + c * 8) * 2u;
                asm volatile("cp.async.cg.shared.global [%0], [%1], 16;\n"
                             :: "r"(dst), "l"(src));
            }
#pragma unroll
            for (int i = 0; i < 4; i++) {
                const int ch = tid + i * 256;
                const int r = ch >> 3, c = ch & 7;
                const __half* src = W + (long)(n0 + r) * ldw + k0 + c * 8;
                const unsigned dst = dB + (unsigned)(r * LDH + c * 8) * 2u;
                asm volatile("cp.async.cg.shared.global [%0], [%1], 16;\n"
                             :: "r"(dst), "l"(src));
            }
        }
        asm volatile("cp.async.commit_group;\n");
    };

    issueStage(0, 0);
    issueStage(1, 1);

    for (int it = 0; it < kIters; it++) {
        asm volatile("cp.async.wait_group 1;\n");
        __syncthreads();
        const int stage = it % STAGES;
        issueStage(it + 2, (it + 2) % STAGES);

        const unsigned baseA = sA + stage * OPB;
        const unsigned baseB = sB + stage * OPB;

#pragma unroll
        for (int kk = 0; kk < BK; kk += 16) {
            unsigned a[4][4], b[4][2];
#pragma unroll
            for (int mi = 0; mi < 4; mi++) {
                const unsigned addr =
                    baseA + (unsigned)(((wm + mi * 16 + aRow) * LDH + kk + aColH) << 1);
                asm volatile(
                    "ldmatrix.sync.aligned.m8n8.x4.shared.b16 {%0,%1,%2,%3}, [%4];"
                    : "=r"(a[mi][0]), "=r"(a[mi][1]), "=r"(a[mi][2]), "=r"(a[mi][3])
                    : "r"(addr));
            }
#pragma unroll
            for (int np = 0; np < 2; np++) {
                const unsigned addr =
                    baseB + (unsigned)(((wn + np * 16 + bRow) * LDH + kk + bColH) << 1);
                asm volatile(
                    "ldmatrix.sync.aligned.m8n8.x4.shared.b16 {%0,%1,%2,%3}, [%4];"
                    : "=r"(b[2 * np][0]), "=r"(b[2 * np][1]),
                      "=r"(b[2 * np + 1][0]), "=r"(b[2 * np + 1][1])
                    : "r"(addr));
            }
#pragma unroll
            for (int mi = 0; mi < 4; mi++)
#pragma unroll
                for (int ni = 0; ni < 4; ni++)
                    mma_fp16(acc[mi][ni], a[mi], b[ni]);
        }
    }

    // epilogue
    const int gid = lane >> 2;
    const int tig = lane & 3;
#pragma unroll
    for (int mi = 0; mi < 4; mi++) {
#pragma unroll
        for (int ni = 0; ni < 4; ni++) {
            const int col = n0 + wn + ni * 8 + tig * 2;
            const float b0 = bias[col];
            const float b1 = bias[col + 1];
            const int r0 = m0 + wm + mi * 16 + gid;
            const int r1 = r0 + 8;
            float v00 = acc[mi][ni][0] + b0;
            float v01 = acc[mi][ni][1] + b1;
            float v10 = acc[mi][ni][2] + b0;
            float v11 = acc[mi][ni][3] + b1;
            if (ACT == 1) {
                v00 = fmaxf(v00, 0.f); v01 = fmaxf(v01, 0.f);
                v10 = fmaxf(v10, 0.f); v11 = fmaxf(v11, 0.f);
            }
            if (OUTH) {
                __half* Ch = (__half*)Cv;
                *reinterpret_cast<__half2*>(&Ch[(long)r0 * ldc + coff + col]) =
                    __floats2half2_rn(v00, v01);
                *reinterpret_cast<__half2*>(&Ch[(long)r1 * ldc + coff + col]) =
                    __floats2half2_rn(v10, v11);
            } else {
                float* Cf = (float*)Cv;
                *reinterpret_cast<float2*>(&Cf[(long)r0 * ldc + coff + col]) =
                    make_float2(v00, v01);
                *reinterpret_cast<float2*>(&Cf[(long)r1 * ldc + coff + col]) =
                    make_float2(v10, v11);
            }
        }
    }
}

// ================= action head (fp16, N=32, tanh) =================
__global__ __launch_bounds__(256)
void gemm_head_h(const __half* __restrict__ A, int lda,
                 const __half* __restrict__ W, int ldw,
                 const float* __restrict__ bias,
                 float* __restrict__ C, int K)
{
    constexpr int BM = 128, BN = 32, BK = 64, LDH = 72;
    __shared__ __align__(16) __half As[BM * LDH];
    __shared__ __align__(16) __half Bs[BN * LDH];
    const unsigned sA = smem_u32(As);
    const unsigned sB = smem_u32(Bs);

    const int m0 = blockIdx.y * BM;
    const int tid = threadIdx.x;
    const int warp = tid >> 5;
    const int lane = tid & 31;
    const int wm = warp * 16;

    const int g = lane >> 3;
    const int r8 = lane & 7;
    const int aRow = (g & 1) * 8 + r8;
    const int aColH = (g >> 1) * 8;
    const int bRow = (g >> 1) * 8 + r8;
    const int bColH = (g & 1) * 8;

    float acc[4][4];
#pragma unroll
    for (int j = 0; j < 4; j++)
#pragma unroll
        for (int v = 0; v < 4; v++) acc[j][v] = 0.0f;

    for (int k0 = 0; k0 < K; k0 += BK) {
        // stage A: 1024 chunks of 16B (8 halves each)
#pragma unroll
        for (int i = 0; i < 4; i++) {
            const int ch = tid + i * 256;
            const int r = ch >> 3, c = ch & 7;
            *reinterpret_cast<uint4*>(&As[r * LDH + c * 8]) =
                *reinterpret_cast<const uint4*>(&A[(long)(m0 + r) * lda + k0 + c * 8]);
        }
        // stage B: 256 chunks of 16B
        {
            const int r = tid >> 3, c = tid & 7;
            if (r < BN)
                *reinterpret_cast<uint4*>(&Bs[r * LDH + c * 8]) =
                    *reinterpret_cast<const uint4*>(&W[(long)r * ldw + k0 + c * 8]);
        }
        __syncthreads();

#pragma unroll
        for (int kk = 0; kk < BK; kk += 16) {
            unsigned a[4], b[4][2];
            {
                const unsigned addr = sA + (unsigned)(((wm + aRow) * LDH + kk + aColH) << 1);
                asm volatile(
                    "ldmatrix.sync.aligned.m8n8.x4.shared.b16 {%0,%1,%2,%3}, [%4];"
                    : "=r"(a[0]), "=r"(a[1]), "=r"(a[2]), "=r"(a[3]) : "r"(addr));
            }
#pragma unroll
            for (int np = 0; np < 2; np++) {
                const unsigned addr = sB + (unsigned)(((np * 16 + bRow) * LDH + kk + bColH) << 1);
                asm volatile(
                    "ldmatrix.sync.aligned.m8n8.x4.shared.b16 {%0,%1,%2,%3}, [%4];"
                    : "=r"(b[2 * np][0]), "=r"(b[2 * np][1]),
                      "=r"(b[2 * np + 1][0]), "=r"(b[2 * np + 1][1])
                    : "r"(addr));
            }
#pragma unroll
            for (int ni = 0; ni < 4; ni++)
                mma_fp16(acc[ni], a, b[ni]);
        }
        __syncthreads();
    }

    const int gid = lane >> 2;
    const int tig = lane & 3;
#pragma unroll
    for (int ni = 0; ni < 4; ni++) {
        const int col = ni * 8 + tig * 2;
        const float b0 = bias[col];
        const float b1 = bias[col + 1];
        const int r0 = m0 + wm + gid;
        const int r1 = r0 + 8;
        C[(long)r0 * 32 + col]     = tanhf(acc[ni][0] + b0);
        C[(long)r0 * 32 + col + 1] = tanhf(acc[ni][1] + b1);
        C[(long)r1 * 32 + col]     = tanhf(acc[ni][2] + b0);
        C[(long)r1 * 32 + col + 1] = tanhf(acc[ni][3] + b1);
    }
}

// ================= GRU elementwise =================
__global__ __launch_bounds__(256)
void gru_kernel(const float* __restrict__ state, float* __restrict__ out)
{
    const int idx = blockIdx.x * blockDim.x + threadIdx.x;
    const int m = idx >> 11;
    const int n = idx & 2047;
    const float* gi = g_gi + (long)m * 6144;
    const float* gh = g_gh + (long)m * 6144;
    const float h0 = state[(long)m * (DE_ + H_) + DE_ + n];

    const float r = 1.0f / (1.0f + expf(-(gi[n] + gh[n])));
    const float z = 1.0f / (1.0f + expf(-(gi[2048 + n] + gh[2048 + n])));
    const float nn = tanhf(gi[4096 + n] + r * gh[4096 + n]);
    const float h1 = (1.0f - z) * nn + z * h0;

    out[(long)B_ * DA_ + (long)m * H_ + n] = 0.5f * h0 + 0.5f * h1;
    g_lasth[(long)m * 4096 + 2048 + n] = __float2half_rn(h1);
}

// ================= fp32 -> fp16 conversion passes =================
__global__ __launch_bounds__(256)
void cvt_half(const float* __restrict__ in, __half* __restrict__ out, int n4)
{
    const int i = blockIdx.x * blockDim.x + threadIdx.x;
    if (i < n4) {
        const float4 v = reinterpret_cast<const float4*>(in)[i];
        reinterpret_cast<__half2*>(out)[2 * i]     = __floats2half2_rn(v.x, v.y);
        reinterpret_cast<__half2*>(out)[2 * i + 1] = __floats2half2_rn(v.z, v.w);
    }
}

// K-padded convert: out [rows][outK] halves, zero beyond inK
__global__ __launch_bounds__(256)
void cvt_half_pad(const float* __restrict__ in, __half* __restrict__ out,
                  int rows, int inK, int outK)
{
    const int i = blockIdx.x * blockDim.x + threadIdx.x;
    const int perRow = outK >> 2;
    if (i >= rows * perRow) return;
    const int row = i / perRow;
    const int c4 = (i % perRow) * 4;
    __half2 h0, h1;
    if (c4 < inK) {
        const float4 v = *reinterpret_cast<const float4*>(in + (long)row * inK + c4);
        h0 = __floats2half2_rn(v.x, v.y);
        h1 = __floats2half2_rn(v.z, v.w);
    } else {
        h0 = __floats2half2_rn(0.f, 0.f);
        h1 = h0;
    }
    *reinterpret_cast<__half2*>(out + (long)row * outK + c4)     = h0;
    *reinterpret_cast<__half2*>(out + (long)row * outK + c4 + 2) = h1;
}

// split state -> env fp16 [B,256] and h0 fp16 [B,2048]
__global__ __launch_bounds__(256)
void split_state_kernel(const float* __restrict__ state,
                        __half* __restrict__ envh, __half* __restrict__ h0h)
{
    const int i = blockIdx.x * blockDim.x + threadIdx.x;
    if (i >= B_ * 576) return;
    const int row = i / 576;
    const int c4 = (i % 576) * 4;
    const float4 v = *reinterpret_cast<const float4*>(state + (long)row * 2304 + c4);
    const __half2 h0 = __floats2half2_rn(v.x, v.y);
    const __half2 h1 = __floats2half2_rn(v.z, v.w);
    __half* dst = (c4 < 256) ? (envh + (long)row * 256 + c4)
                             : (h0h + (long)row * 2048 + (c4 - 256));
    *reinterpret_cast<__half2*>(dst)     = h0;
    *reinterpret_cast<__half2*>(dst + 2) = h1;
}

extern "C" void kernel_launch(void* const* d_in, const int* in_sizes, int n_in,
                              void* d_out, int out_size)
{
    const float* state  = (const float*)d_in[0];
    const float* pa     = (const float*)d_in[1];
    const float* W_o    = (const float*)d_in[2];
    const float* b_o    = (const float*)d_in[3];
    const float* W_a    = (const float*)d_in[4];
    const float* b_a    = (const float*)d_in[5];
    const float* W_post = (const float*)d_in[6];
    const float* b_post = (const float*)d_in[7];
    const float* W_ih   = (const float*)d_in[8];
    const float* W_hh   = (const float*)d_in[9];
    const float* b_ih   = (const float*)d_in[10];
    const float* b_hh   = (const float*)d_in[11];
    const float* W3     = (const float*)d_in[12];
    const float* b3     = (const float*)d_in[13];
    float* out = (float*)d_out;

    float *gi, *gh;
    __half *xh, *lasth, *Wih_h, *Whh_h, *h0h, *envh, *pah, *Woh, *Wah, *Wposth, *W3h;
    cudaGetSymbolAddress((void**)&gi,     g_gi);
    cudaGetSymbolAddress((void**)&gh,     g_gh);
    cudaGetSymbolAddress((void**)&xh,     g_xh);
    cudaGetSymbolAddress((void**)&lasth,  g_lasth);
    cudaGetSymbolAddress((void**)&Wih_h,  g_Wih_h);
    cudaGetSymbolAddress((void**)&Whh_h,  g_Whh_h);
    cudaGetSymbolAddress((void**)&h0h,    g_h0h);
    cudaGetSymbolAddress((void**)&envh,   g_envh);
    cudaGetSymbolAddress((void**)&pah,    g_pah);
    cudaGetSymbolAddress((void**)&Woh,    g_Woh);
    cudaGetSymbolAddress((void**)&Wah,    g_Wah);
    cudaGetSymbolAddress((void**)&Wposth, g_Wposth);
    cudaGetSymbolAddress((void**)&W3h,    g_W3h);

    const int SMEMH = 3 * 2 * 128 * 72 * 2;  // 110592 B
    cudaFuncSetAttribute(gemm_h<1, 1>, cudaFuncAttributeMaxDynamicSharedMemorySize, SMEMH);
    cudaFuncSetAttribute(gemm_h<0, 0>, cudaFuncAttributeMaxDynamicSharedMemorySize, SMEMH);

    const dim3 blk(256);

    // ---- fp16 conversion passes ----
    split_state_kernel<<<(B_ * 576 + 255) / 256, blk>>>(state, envh, h0h);
    cvt_half_pad<<<(B_ * 16 + 255) / 256, blk>>>(pa, pah, B_, 32, 64);
    cvt_half<<<(2048 * 256 / 4 + 255) / 256, blk>>>(W_o, Woh, 2048 * 256 / 4);
    cvt_half_pad<<<(2048 * 16 + 255) / 256, blk>>>(W_a, Wah, 2048, 32, 64);
    cvt_half<<<(2048 * 256 / 4 + 255) / 256, blk>>>(W_post, Wposth, 2048 * 256 / 4);
    cvt_half<<<(6144 * 4096 / 4 + 255) / 256, blk>>>(W_ih, Wih_h, 6144 * 4096 / 4);
    cvt_half<<<(6144 * 2048 / 4 + 255) / 256, blk>>>(W_hh, Whh_h, 6144 * 2048 / 4);
    cvt_half<<<(32 * 4096 / 4 + 255) / 256, blk>>>(W3, W3h, 32 * 4096 / 4);

    // ---- feature GEMMs (relu, fp16 out) ----
    gemm_h<1, 1><<<dim3(16, 64), blk, SMEMH>>>(envh, 256, Woh, 256, b_o, xh, 4096, 0, 4);
    gemm_h<1, 1><<<dim3(16, 64), blk, SMEMH>>>(pah, 64, Wah, 64, b_a, xh, 4096, 2048, 1);
    gemm_h<1, 1><<<dim3(16, 64), blk, SMEMH>>>(envh, 256, Wposth, 256, b_post, lasth, 4096, 0, 4);

    // ---- big gate GEMMs (fp32 out) ----
    gemm_h<0, 0><<<dim3(48, 64), blk, SMEMH>>>(xh, 4096, Wih_h, 4096, b_ih, gi, 6144, 0, 64);
    gemm_h<0, 0><<<dim3(48, 64), blk, SMEMH>>>(h0h, 2048, Whh_h, 2048, b_hh, gh, 6144, 0, 32);

    // ---- GRU elementwise ----
    gru_kernel<<<(B_ * H_) / 256, blk>>>(state, out);

    // ---- action head ----
    gemm_head_h<<<dim3(1, 64), blk>>>(lasth, 4096, W3h, 4096, b3, out, 4096);
}